// round 12
// baseline (speedup 1.0000x reference)
#include <cuda_runtime.h>
#include <cuda_bf16.h>

// Dual marching cubes, GRID=192, ISO=0.
// R12: R11 (consolidated floor kernel) at block=512. The kernel sits at the
// LTS byte ceiling (~5.7 TB/s stores = ~11.5 TB/s L2-array traffic = chip cap);
// output bytes are mandated, so this is the hardware floor for the problem.
// Output (float32, concatenated, reference order):
//   verts  [193^3 * 3]       at V_OFF  = 0
//   vmask  [193^3]           at VM_OFF = 21,567,171
//   quads  [3*193*192*192*4] at Q_OFF  = 28,756,228
//   qmask  [3*193*192*192]   at QM_OFF = 114,133,252

#define GD   192
#define C    193
#define C2   (C*C)          // 37249
#define NC   (C*C*C)        // 7,189,057
#define NEX  (C*GD*GD)      // 7,114,752
#define NQ   (3*NEX)
#define V_OFF  0
#define VM_OFF (3*NC)
#define Q_OFF  (VM_OFF + NC)
#define QM_OFF (Q_OFF + 4*NQ)

#define BT   512
#define NVB  ((NC + BT - 1) / BT)   // 14042 blocks

__global__ void __launch_bounds__(BT, 4)
dmc12(const float* __restrict__ g, float* __restrict__ out)
{
    __shared__ float s[BT * 3];
    const int tid  = threadIdx.x;
    const int base = blockIdx.x * BT;
    const int idx  = base + tid;
    const bool active = idx < NC;
    const int cidx = active ? idx : (NC - 1);

    // cidx = (a*C + b)*C + c
    const int c  = cidx % C;
    const int t2 = cidx / C;
    const int b  = t2 % C;
    const int a  = t2 / C;

    // quad output flat offsets (r = b*C + c = cidx - a*C2):
    //   o0 = 36864*a + r - b - 193
    //   o1 = 37056*(a-1) + r - b - 1
    //   o2 = 37056*(a-1) + r - 193
    const int r  = cidx - a * C2;
    const int t1 = 37056 * a - 37056 + r;
    const int o0 = 36864 * a + r - b - 193;
    const int o1 = t1 - b - 1;
    const int o2 = t1 - 193;
    const bool q0 = active & (b >= 1) & (c >= 1);
    const bool q1 = active & (a >= 1) & (c >= 1);
    const bool q2 = active & (a >= 1) & (b >= 1);

    // ---------------- quads first: pure function of index, store early ----------------
    {
        const float fb = (float)cidx;
        float4* qb = (float4*)(out + Q_OFF);
        if (q0) __stcs(qb + o0,           make_float4(fb - 194.f,   fb - 1.f,   fb, fb - 193.f));
        if (q1) __stcs(qb + NEX + o1,     make_float4(fb - 37250.f, fb - 1.f,   fb, fb - 37249.f));
        if (q2) __stcs(qb + 2 * NEX + o2, make_float4(fb - 37442.f, fb - 193.f, fb, fb - 37249.f));
    }

    // ---------------- corner loads ----------------
    // corner k: dx=k&1 (a), dy=(k>>1)&1 (b), dz=(k>>2)&1 (c); P[a+dx, b+dy, c+dz]
    float v[8];
    const int ga = a - 1, gb = b - 1, gc = c - 1;
    const bool interior = (a >= 1) & (a <= GD - 1) & (b >= 1) & (b <= GD - 1) & (c >= 1) & (c <= GD - 1);
    if (interior) {
        const float* p = g + ((ga * GD + gb) * GD + gc);
        #pragma unroll
        for (int k = 0; k < 8; k++) {
            int dx = k & 1, dy = (k >> 1) & 1, dz = (k >> 2) & 1;
            v[k] = __ldg(p + (dx * GD + dy) * GD + dz);
        }
    } else {
        #pragma unroll
        for (int k = 0; k < 8; k++) {
            int x = ga + (k & 1), y = gb + ((k >> 1) & 1), z = gc + ((k >> 2) & 1);
            bool in = ((unsigned)x < (unsigned)GD) & ((unsigned)y < (unsigned)GD) & ((unsigned)z < (unsigned)GD);
            v[k] = in ? __ldg(g + (x * GD + y) * GD + z) : 1.0f;   // pad = iso+1
        }
    }

    // ---------------- qmask (needs only 4 corner signs) ----------------
    {
        const bool s0 = v[0] < 0.f, s1 = v[1] < 0.f, s2v = v[2] < 0.f, s4v = v[4] < 0.f;
        if (q0) __stcs(out + QM_OFF + o0,           (s0 != s1)  ? 1.f : 0.f);
        if (q1) __stcs(out + QM_OFF + NEX + o1,     (s0 != s2v) ? 1.f : 0.f);
        if (q2) __stcs(out + QM_OFF + 2 * NEX + o2, (s0 != s4v) ? 1.f : 0.f);
    }

    // ---------------- vertex: 12-edge crossing mean ----------------
    const int EA[12] = {0,2,4,6, 0,1,4,5, 0,1,2,3};
    float sx = 0.f, sy = 0.f, sz = 0.f, cnt = 0.f;
    #pragma unroll
    for (int e = 0; e < 12; e++) {
        int axis = e >> 2;
        int A = EA[e];
        int B = A + (1 << axis);
        float vA = v[A], vB = v[B];
        bool m = (vA < 0.f) != (vB < 0.f);
        if (m) {
            float tt = __fdividef(vA, vA - vB);   // == (0 - vA)/(vB - vA)
            float px = (axis == 0) ? tt : (float)(A & 1);
            float py = (axis == 1) ? tt : (float)((A >> 1) & 1);
            float pz = (axis == 2) ? tt : (float)((A >> 2) & 1);
            sx += px; sy += py; sz += pz; cnt += 1.f;
        }
    }

    const float inv = __fdividef(1.f, fmaxf(cnt, 1.f));
    const float nrm = 1.0f / (float)(GD - 1);
    float fx = ((float)a + sx * inv - 1.f) * nrm;
    float fy = ((float)b + sy * inv - 1.f) * nrm;
    float fz = ((float)c + sz * inv - 1.f) * nrm;

    if (active) __stcs(out + VM_OFF + idx, (cnt > 0.f) ? 1.f : 0.f);

    // ---------------- vert stores: stage stride-3 via smem -> coalesced ----------------
    s[tid * 3 + 0] = fx;
    s[tid * 3 + 1] = fy;
    s[tid * 3 + 2] = fz;
    __syncthreads();
    const int outb = base * 3;
    #pragma unroll
    for (int i = 0; i < 3; i++) {
        int o = outb + tid + i * BT;
        if (o < 3 * NC) __stcs(out + V_OFF + o, s[tid + i * BT]);
    }
}

extern "C" void kernel_launch(void* const* d_in, const int* in_sizes, int n_in,
                              void* d_out, int out_size)
{
    const float* g = (const float*)d_in[0];
    float* out = (float*)d_out;
    dmc12<<<NVB, BT>>>(g, out);
}

// round 13
// speedup vs baseline: 1.0221x; 1.0221x over previous
#include <cuda_runtime.h>
#include <cuda_bf16.h>

// Dual marching cubes, GRID=192, ISO=0.  FINAL (R11 configuration).
// 1 thread = 1 cell: vertex (12-edge crossing mean), vmask, and the 3 quads/
// qmasks anchored at the cell's own P-coordinate (signs reuse the corner loads;
// quad cell-ids are cidx +- compile-time constants, exact in fp32).
// At the LTS byte ceiling: ~5.7 TB/s stores = ~11.5 TB/s L2-array traffic =
// chip cap; output bytes are mandated, so this is the hardware floor.
// Output (float32, concatenated, reference order):
//   verts  [193^3 * 3]       at V_OFF  = 0
//   vmask  [193^3]           at VM_OFF = 21,567,171
//   quads  [3*193*192*192*4] at Q_OFF  = 28,756,228
//   qmask  [3*193*192*192]   at QM_OFF = 114,133,252

#define GD   192
#define C    193
#define C2   (C*C)          // 37249
#define NC   (C*C*C)        // 7,189,057
#define NEX  (C*GD*GD)      // 7,114,752
#define NQ   (3*NEX)
#define V_OFF  0
#define VM_OFF (3*NC)
#define Q_OFF  (VM_OFF + NC)
#define QM_OFF (Q_OFF + 4*NQ)
#define NVB ((NC + 255) / 256)    // 28083 blocks

__global__ void __launch_bounds__(256, 8)
dmc_final(const float* __restrict__ g, float* __restrict__ out)
{
    __shared__ float s[768];
    const int tid  = threadIdx.x;
    const int base = blockIdx.x * 256;
    const int idx  = base + tid;
    const bool active = idx < NC;
    const int cidx = active ? idx : (NC - 1);

    // cidx = (a*C + b)*C + c
    const int c  = cidx % C;
    const int t2 = cidx / C;
    const int b  = t2 % C;
    const int a  = t2 / C;

    // quad output flat offsets (r = b*C + c = cidx - a*C2):
    //   o0 = (a*192 + b-1)*192 + (c-1) = 36864*a + r - b - 193
    //   o1 = ((a-1)*193 + b)*192 + c-1 = 37056*(a-1) + r - b - 1
    //   o2 = ((a-1)*192 + b-1)*193 + c = 37056*(a-1) + r - 193
    const int r  = cidx - a * C2;
    const int t1 = 37056 * a - 37056 + r;
    const int o0 = 36864 * a + r - b - 193;
    const int o1 = t1 - b - 1;
    const int o2 = t1 - 193;
    const bool q0 = active & (b >= 1) & (c >= 1);
    const bool q1 = active & (a >= 1) & (c >= 1);
    const bool q2 = active & (a >= 1) & (b >= 1);

    // ---------------- quads first: pure function of index, store early ----------------
    {
        const float fb = (float)cidx;
        float4* qb = (float4*)(out + Q_OFF);
        if (q0) __stcs(qb + o0,           make_float4(fb - 194.f,   fb - 1.f,   fb, fb - 193.f));
        if (q1) __stcs(qb + NEX + o1,     make_float4(fb - 37250.f, fb - 1.f,   fb, fb - 37249.f));
        if (q2) __stcs(qb + 2 * NEX + o2, make_float4(fb - 37442.f, fb - 193.f, fb, fb - 37249.f));
    }

    // ---------------- corner loads ----------------
    // corner k: dx=k&1 (a), dy=(k>>1)&1 (b), dz=(k>>2)&1 (c); P[a+dx, b+dy, c+dz]
    float v[8];
    const int ga = a - 1, gb = b - 1, gc = c - 1;
    const bool interior = (a >= 1) & (a <= GD - 1) & (b >= 1) & (b <= GD - 1) & (c >= 1) & (c <= GD - 1);
    if (interior) {
        const float* p = g + ((ga * GD + gb) * GD + gc);
        #pragma unroll
        for (int k = 0; k < 8; k++) {
            int dx = k & 1, dy = (k >> 1) & 1, dz = (k >> 2) & 1;
            v[k] = __ldg(p + (dx * GD + dy) * GD + dz);
        }
    } else {
        #pragma unroll
        for (int k = 0; k < 8; k++) {
            int x = ga + (k & 1), y = gb + ((k >> 1) & 1), z = gc + ((k >> 2) & 1);
            bool in = ((unsigned)x < (unsigned)GD) & ((unsigned)y < (unsigned)GD) & ((unsigned)z < (unsigned)GD);
            v[k] = in ? __ldg(g + (x * GD + y) * GD + z) : 1.0f;   // pad = iso+1
        }
    }

    // ---------------- qmask (needs only 4 corner signs) ----------------
    {
        const bool s0 = v[0] < 0.f, s1 = v[1] < 0.f, s2v = v[2] < 0.f, s4v = v[4] < 0.f;
        if (q0) __stcs(out + QM_OFF + o0,           (s0 != s1)  ? 1.f : 0.f);
        if (q1) __stcs(out + QM_OFF + NEX + o1,     (s0 != s2v) ? 1.f : 0.f);
        if (q2) __stcs(out + QM_OFF + 2 * NEX + o2, (s0 != s4v) ? 1.f : 0.f);
    }

    // ---------------- vertex: 12-edge crossing mean ----------------
    const int EA[12] = {0,2,4,6, 0,1,4,5, 0,1,2,3};
    float sx = 0.f, sy = 0.f, sz = 0.f, cnt = 0.f;
    #pragma unroll
    for (int e = 0; e < 12; e++) {
        int axis = e >> 2;
        int A = EA[e];
        int B = A + (1 << axis);
        float vA = v[A], vB = v[B];
        bool m = (vA < 0.f) != (vB < 0.f);
        if (m) {
            float tt = __fdividef(vA, vA - vB);   // == (0 - vA)/(vB - vA)
            float px = (axis == 0) ? tt : (float)(A & 1);
            float py = (axis == 1) ? tt : (float)((A >> 1) & 1);
            float pz = (axis == 2) ? tt : (float)((A >> 2) & 1);
            sx += px; sy += py; sz += pz; cnt += 1.f;
        }
    }

    const float inv = __fdividef(1.f, fmaxf(cnt, 1.f));
    const float nrm = 1.0f / (float)(GD - 1);
    float fx = ((float)a + sx * inv - 1.f) * nrm;
    float fy = ((float)b + sy * inv - 1.f) * nrm;
    float fz = ((float)c + sz * inv - 1.f) * nrm;

    if (active) __stcs(out + VM_OFF + idx, (cnt > 0.f) ? 1.f : 0.f);

    // ---------------- vert stores: stage stride-3 via smem -> coalesced ----------------
    s[tid * 3 + 0] = fx;
    s[tid * 3 + 1] = fy;
    s[tid * 3 + 2] = fz;
    __syncthreads();
    const int outb = base * 3;
    #pragma unroll
    for (int i = 0; i < 3; i++) {
        int o = outb + tid + i * 256;
        if (o < 3 * NC) __stcs(out + V_OFF + o, s[tid + i * 256]);
    }
}

extern "C" void kernel_launch(void* const* d_in, const int* in_sizes, int n_in,
                              void* d_out, int out_size)
{
    const float* g = (const float*)d_in[0];
    float* out = (float*)d_out;
    dmc_final<<<NVB, 256>>>(g, out);
}